// round 3
// baseline (speedup 1.0000x reference)
#include <cuda_runtime.h>
#include <math_constants.h>

#define NB 64
#define NC 1000
#define HW 196
#define NF4 49
#define C4L2E 5.770780163555852f          // 4 * log2(e)
#define LN2   0.6931471805599453f
#define L2E   1.4426950408889634f
#define CLIP2 (-19.931568569324174f)      // log2(1e-6)
#define DEADB (-12000.0f)                 // bias: 2^(u+DEADB) == 0

__device__ float g_abl[NB * NC];
__device__ float g_kp[NB * NC];
__device__ float g_ace[NB];
__device__ float g_kld[NB];

__device__ __forceinline__ float ex2f(float x) {
    float r; asm("ex2.approx.f32 %0, %1;" : "=f"(r) : "f"(x)); return r;
}
__device__ __forceinline__ float warpSum(float v) {
#pragma unroll
    for (int o = 16; o; o >>= 1) v += __shfl_xor_sync(0xffffffffu, v, o);
    return v;
}
__device__ __forceinline__ float warpMax(float v) {
#pragma unroll
    for (int o = 16; o; o >>= 1) v = fmaxf(v, __shfl_xor_sync(0xffffffffu, v, o));
    return v;
}

// ---------------------------------------------------------------------------
// K1: warp-per-row, fully branch-free.
// Row = 49 float4. Lane L owns slot L and slot (32 + min(L,16)).
// Lanes 17..31's second slot is a duplicate of slot 48; its contribution is
// arithmetically zeroed: f=0 (kp/abl-neg), m=0 (abl-pos), bias=-12000 (den).
// Base-2 math: u = C4L2E*cv + bias; den = sum 2^u; L2 = log2(den);
// logp = ln2*(u - L2); kp = -ln2 * sum_fg max(u-L2, CLIP2).
// ---------------------------------------------------------------------------
__global__ __launch_bounds__(256, 5) void k1(const float* __restrict__ cams,
                                             const int* __restrict__ y0,
                                             const int* __restrict__ labels) {
    __shared__ float4 s_tn4[NF4];   // negated target row
    __shared__ float4 s_f4[NF4];    // fg mask as float

    const int b = blockIdx.x;
    const int tid = threadIdx.x;
    const int label = __ldg(labels + b);
    const float* base = cams + (size_t)b * NC * HW;

    if (tid < HW) {
        ((float*)s_tn4)[tid] = -__ldg(base + (size_t)label * HW + tid);
        ((float*)s_f4)[tid]  = (float)__ldg(y0 + b * HW + tid);
    }
    __syncthreads();

    const int warp = tid >> 5;
    const int lane = tid & 31;
    const bool live = lane < (NF4 - 32);        // lanes 0..16 own real 2nd slot
    const int idx2 = 32 + (live ? lane : 16);   // clamped (slot 48 is valid)
    const float m1 = live ? 1.0f : 0.0f;
    const float bias1 = live ? 0.0f : DEADB;

    const float4 tn0 = s_tn4[lane];
    const float4 f0  = s_f4[lane];
    float4 tn1 = s_tn4[idx2];
    float4 f1  = s_f4[idx2];
    if (!live) { tn1 = make_float4(0.f,0.f,0.f,0.f); f1 = make_float4(0.f,0.f,0.f,0.f); }

    const int CPB = NC / 25;                    // 40 classes per block
    const int c0 = blockIdx.y * CPB;

    for (int cl = warp; cl < CPB; cl += 8) {
        const int c = c0 + cl;
        const float4* row4 = (const float4*)(base + (size_t)c * HW);
        const float4 a0 = __ldg(row4 + lane);
        const float4 a1 = __ldg(row4 + idx2);

        float u[8];
        float den = 0.f, ap = 0.f, an = 0.f;

        {   // slot 0: always live (m = 1)
            float cv;
            cv = a0.x + tn0.x; u[0] = C4L2E * cv; den += ex2f(u[0]);
            ap += fabsf(cv); an = fmaf(f0.x, fabsf(cv) + cv, an);
            cv = a0.y + tn0.y; u[1] = C4L2E * cv; den += ex2f(u[1]);
            ap += fabsf(cv); an = fmaf(f0.y, fabsf(cv) + cv, an);
            cv = a0.z + tn0.z; u[2] = C4L2E * cv; den += ex2f(u[2]);
            ap += fabsf(cv); an = fmaf(f0.z, fabsf(cv) + cv, an);
            cv = a0.w + tn0.w; u[3] = C4L2E * cv; den += ex2f(u[3]);
            ap += fabsf(cv); an = fmaf(f0.w, fabsf(cv) + cv, an);
        }
        {   // slot 1: masked by m1 / f1 / bias1
            float cv;
            cv = a1.x + tn1.x; u[4] = fmaf(C4L2E, cv, bias1); den += ex2f(u[4]);
            ap = fmaf(m1, fabsf(cv), ap); an = fmaf(f1.x, fabsf(cv) + cv, an);
            cv = a1.y + tn1.y; u[5] = fmaf(C4L2E, cv, bias1); den += ex2f(u[5]);
            ap = fmaf(m1, fabsf(cv), ap); an = fmaf(f1.y, fabsf(cv) + cv, an);
            cv = a1.z + tn1.z; u[6] = fmaf(C4L2E, cv, bias1); den += ex2f(u[6]);
            ap = fmaf(m1, fabsf(cv), ap); an = fmaf(f1.z, fabsf(cv) + cv, an);
            cv = a1.w + tn1.w; u[7] = fmaf(C4L2E, cv, bias1); den += ex2f(u[7]);
            ap = fmaf(m1, fabsf(cv), ap); an = fmaf(f1.w, fabsf(cv) + cv, an);
        }

        den = warpSum(den);
        const float L2 = __log2f(den);          // computed per-lane (1 warp instr)

        float ka = 0.f;
        ka = fmaf(f0.x, fmaxf(u[0] - L2, CLIP2), ka);
        ka = fmaf(f0.y, fmaxf(u[1] - L2, CLIP2), ka);
        ka = fmaf(f0.z, fmaxf(u[2] - L2, CLIP2), ka);
        ka = fmaf(f0.w, fmaxf(u[3] - L2, CLIP2), ka);
        ka = fmaf(f1.x, fmaxf(u[4] - L2, CLIP2), ka);
        ka = fmaf(f1.y, fmaxf(u[5] - L2, CLIP2), ka);
        ka = fmaf(f1.z, fmaxf(u[6] - L2, CLIP2), ka);
        ka = fmaf(f1.w, fmaxf(u[7] - L2, CLIP2), ka);

        float abl = warpSum(ap - an);
        ka = warpSum(ka);

        if (lane == 0) {
            g_abl[b * NC + c] = abl;
            g_kp[b * NC + c]  = -LN2 * ka;
        }
    }
}

// ---------------------------------------------------------------------------
// K2: one warp per batch. grid = 8, block = 256 (8 warps). No __syncthreads.
// ---------------------------------------------------------------------------
__global__ __launch_bounds__(256) void k2(const int* __restrict__ y0,
                                          const int* __restrict__ labels) {
    const int warp = threadIdx.x >> 5;
    const int lane = threadIdx.x & 31;
    const int b = blockIdx.x * 8 + warp;
    const float* abl = g_abl + b * NC;
    const float* kpp = g_kp + b * NC;

    float n1 = 0.f;
    for (int p = lane; p < HW; p += 32) n1 += (float)__ldg(y0 + b * HW + p);

    float mx = -CUDART_INF_F;
    for (int c = lane; c < NC; c += 32) mx = fmaxf(mx, abl[c]);
    mx = warpMax(mx);

    float se = 0.f, sa = 0.f, sk = 0.f;
    for (int c = lane; c < NC; c += 32) {
        const float a = abl[c];
        se += ex2f((a - mx) * L2E);
        sa += a;
        sk += kpp[c];
    }
    se = warpSum(se); sa = warpSum(sa); sk = warpSum(sk); n1 = warpSum(n1);

    if (lane == 0) {
        const float L = __logf(se);
        const int lab = __ldg(labels + b);
        const float al = abl[lab];
        const float ace = -(0.9f * (al - mx - L) +
                            1e-4f * (sa - (float)NC * (mx + L)));
        float p1 = 0.f;
        if (n1 > 0.f) p1 = 1.f / (n1 + ((float)HW - n1) * __expf(-10.f));
        g_ace[b] = ace;
        g_kld[b] = p1 * sk;
    }
}

// ---------------------------------------------------------------------------
// K3: 64 -> 1. One warp.
// ---------------------------------------------------------------------------
__global__ void k3(float* __restrict__ out) {
    const int lane = threadIdx.x;
    float a = g_ace[lane] + g_ace[lane + 32];
    float k = g_kld[lane] + g_kld[lane + 32];
    a = warpSum(a);
    k = warpSum(k);
    if (lane == 0) out[0] = (a + 0.5f * k) * (1.0f / NB);
}

extern "C" void kernel_launch(void* const* d_in, const int* in_sizes, int n_in,
                              void* d_out, int out_size) {
    const float* cams  = (const float*)d_in[0];
    const int* y0      = (const int*)d_in[1];
    const int* labels  = (const int*)d_in[2];
    float* out = (float*)d_out;

    k1<<<dim3(NB, 25), 256>>>(cams, y0, labels);
    k2<<<8, 256>>>(y0, labels);
    k3<<<1, 32>>>(out);
}

// round 4
// speedup vs baseline: 1.1498x; 1.1498x over previous
#include <cuda_runtime.h>
#include <math_constants.h>

#define NB 64
#define NC 1000
#define HW 196
#define NF4 49
#define C4L2E 5.770780163555852f          // 4 * log2(e)
#define LN2   0.6931471805599453f
#define L2E   1.4426950408889634f
#define CLIP2 (-19.931568569324174f)      // log2(1e-6)
#define DEADB (-12000.0f)                 // bias: 2^(u+DEADB) == 0

__device__ float g_abl[NB * NC];
__device__ float g_kp[NB * NC];
__device__ float g_ace[NB];
__device__ float g_kld[NB];
__device__ int   g_done = 0;

__device__ __forceinline__ float ex2f(float x) {
    float r; asm("ex2.approx.f32 %0, %1;" : "=f"(r) : "f"(x)); return r;
}
__device__ __forceinline__ float warpSum(float v) {
#pragma unroll
    for (int o = 16; o; o >>= 1) v += __shfl_xor_sync(0xffffffffu, v, o);
    return v;
}
__device__ __forceinline__ float warpMax(float v) {
#pragma unroll
    for (int o = 16; o; o >>= 1) v = fmaxf(v, __shfl_xor_sync(0xffffffffu, v, o));
    return v;
}

// ---------------------------------------------------------------------------
// K1: warp-per-row, branch-free. grid=(NB,25), block=256 (8 warps, 5 rows/warp).
// Lane L owns float4 slot L and slot 32+min(L,16); dead second slots are
// arithmetically zeroed (f=0, m=0, exp bias=-12000).
// ka uses: sum_fg max(u-L2,clip) = sum_fg max(u, L2+clip) - n1*L2, with n1
// (row-invariant fg count) hoisted out of the row loop.
// ---------------------------------------------------------------------------
__global__ __launch_bounds__(256, 6) void k1(const float* __restrict__ cams,
                                             const int* __restrict__ y0,
                                             const int* __restrict__ labels) {
    __shared__ float4 s_tn4[NF4];   // negated target row
    __shared__ float4 s_f4[NF4];    // fg mask as float

    const int b = blockIdx.x;
    const int tid = threadIdx.x;
    const int label = __ldg(labels + b);
    const float* base = cams + (size_t)b * NC * HW;

    if (tid < HW) {
        ((float*)s_tn4)[tid] = -__ldg(base + (size_t)label * HW + tid);
        ((float*)s_f4)[tid]  = (float)__ldg(y0 + b * HW + tid);
    }
    __syncthreads();

    const int warp = tid >> 5;
    const int lane = tid & 31;
    const bool live = lane < (NF4 - 32);
    const int idx2 = 32 + (live ? lane : 16);
    const float m1 = live ? 1.0f : 0.0f;
    const float bias1 = live ? 0.0f : DEADB;

    const float4 tn0 = s_tn4[lane];
    const float4 f0  = s_f4[lane];
    float4 tn1 = s_tn4[idx2];
    float4 f1  = s_f4[idx2];
    if (!live) { tn1 = make_float4(0.f,0.f,0.f,0.f); f1 = make_float4(0.f,0.f,0.f,0.f); }

    // row-invariant fg count (n1) — hoisted out of the loop
    float n1 = (f0.x + f0.y) + (f0.z + f0.w) + (f1.x + f1.y) + (f1.z + f1.w);
    n1 = warpSum(n1);

    const int CPB = NC / 25;                    // 40 classes per block
    const int c0 = blockIdx.y * CPB;

    const float4* row4 = (const float4*)(base + (size_t)(c0 + warp) * HW);
    const size_t rstep = (size_t)8 * NF4;       // 8 rows ahead per iteration

#pragma unroll 1
    for (int cl = warp; cl < CPB; cl += 8, row4 += rstep) {
        const float4 a0 = __ldg(row4 + lane);
        const float4 a1 = __ldg(row4 + idx2);

        float u[8];
        float den = 0.f, ap = 0.f, an = 0.f;

        {   // slot 0: always live
            float cv;
            cv = a0.x + tn0.x; u[0] = C4L2E * cv; den += ex2f(u[0]);
            ap += fabsf(cv); an = fmaf(f0.x, fabsf(cv) + cv, an);
            cv = a0.y + tn0.y; u[1] = C4L2E * cv; den += ex2f(u[1]);
            ap += fabsf(cv); an = fmaf(f0.y, fabsf(cv) + cv, an);
            cv = a0.z + tn0.z; u[2] = C4L2E * cv; den += ex2f(u[2]);
            ap += fabsf(cv); an = fmaf(f0.z, fabsf(cv) + cv, an);
            cv = a0.w + tn0.w; u[3] = C4L2E * cv; den += ex2f(u[3]);
            ap += fabsf(cv); an = fmaf(f0.w, fabsf(cv) + cv, an);
        }
        {   // slot 1: masked (m1 / f1 / bias1)
            float cv;
            cv = a1.x + tn1.x; u[4] = fmaf(C4L2E, cv, bias1); den += ex2f(u[4]);
            ap = fmaf(m1, fabsf(cv), ap); an = fmaf(f1.x, fabsf(cv) + cv, an);
            cv = a1.y + tn1.y; u[5] = fmaf(C4L2E, cv, bias1); den += ex2f(u[5]);
            ap = fmaf(m1, fabsf(cv), ap); an = fmaf(f1.y, fabsf(cv) + cv, an);
            cv = a1.z + tn1.z; u[6] = fmaf(C4L2E, cv, bias1); den += ex2f(u[6]);
            ap = fmaf(m1, fabsf(cv), ap); an = fmaf(f1.z, fabsf(cv) + cv, an);
            cv = a1.w + tn1.w; u[7] = fmaf(C4L2E, cv, bias1); den += ex2f(u[7]);
            ap = fmaf(m1, fabsf(cv), ap); an = fmaf(f1.w, fabsf(cv) + cv, an);
        }

        den = warpSum(den);
        const float L2 = __log2f(den);
        const float Lc = L2 + CLIP2;

        float ka = 0.f;
        ka = fmaf(f0.x, fmaxf(u[0], Lc), ka);
        ka = fmaf(f0.y, fmaxf(u[1], Lc), ka);
        ka = fmaf(f0.z, fmaxf(u[2], Lc), ka);
        ka = fmaf(f0.w, fmaxf(u[3], Lc), ka);
        ka = fmaf(f1.x, fmaxf(u[4], Lc), ka);
        ka = fmaf(f1.y, fmaxf(u[5], Lc), ka);
        ka = fmaf(f1.z, fmaxf(u[6], Lc), ka);
        ka = fmaf(f1.w, fmaxf(u[7], Lc), ka);

        float abl = warpSum(ap - an);
        ka = warpSum(ka);

        if (lane == 0) {
            const int c = c0 + cl;
            g_abl[b * NC + c] = abl;
            g_kp[b * NC + c]  = -LN2 * (ka - n1 * L2);
        }
    }
}

// ---------------------------------------------------------------------------
// K2 (fused with final reduce): grid=NB, block=256. Block b reduces batch b;
// the last block to finish reduces the 64 per-batch partials to the scalar.
// ---------------------------------------------------------------------------
__global__ __launch_bounds__(256) void k2(const int* __restrict__ y0,
                                          const int* __restrict__ labels,
                                          float* __restrict__ out) {
    __shared__ float sh[8];
    __shared__ float s_bmax;
    __shared__ int s_last;

    const int b = blockIdx.x;
    const int tid = threadIdx.x;
    const int warp = tid >> 5;
    const int lane = tid & 31;
    const float* abl = g_abl + b * NC;
    const float* kpp = g_kp + b * NC;

    float n1 = (tid < HW) ? (float)__ldg(y0 + b * HW + tid) : 0.f;

    // pass 1: batch max of ablation
    float mx = -CUDART_INF_F;
    for (int c = tid; c < NC; c += 256) mx = fmaxf(mx, abl[c]);
    mx = warpMax(mx);
    if (lane == 0) sh[warp] = mx;
    __syncthreads();
    if (warp == 0) {
        float m2 = (lane < 8) ? sh[lane] : -CUDART_INF_F;
        m2 = warpMax(m2);
        if (lane == 0) s_bmax = m2;
    }
    __syncthreads();
    const float bmax = s_bmax;

    // pass 2: sumexp, sum, kpart-sum
    float se = 0.f, sa = 0.f, sk = 0.f;
    for (int c = tid; c < NC; c += 256) {
        const float a = abl[c];
        se += ex2f((a - bmax) * L2E);
        sa += a;
        sk += kpp[c];
    }
    se = warpSum(se); sa = warpSum(sa); sk = warpSum(sk); n1 = warpSum(n1);

    // cross-warp combine (fixed order -> deterministic)
    __syncthreads();
    if (lane == 0) sh[warp] = se;
    __syncthreads();
    if (tid == 0) { float t = 0.f; for (int i = 0; i < 8; i++) t += sh[i]; s_bmax = t; }
    __syncthreads();
    const float se_t = s_bmax;
    __syncthreads();
    if (lane == 0) sh[warp] = sa;
    __syncthreads();
    if (tid == 0) { float t = 0.f; for (int i = 0; i < 8; i++) t += sh[i]; s_bmax = t; }
    __syncthreads();
    const float sa_t = s_bmax;
    __syncthreads();
    if (lane == 0) sh[warp] = sk;
    __syncthreads();
    if (tid == 0) { float t = 0.f; for (int i = 0; i < 8; i++) t += sh[i]; s_bmax = t; }
    __syncthreads();
    const float sk_t = s_bmax;
    __syncthreads();
    if (lane == 0) sh[warp] = n1;
    __syncthreads();

    if (tid == 0) {
        float n1t = 0.f;
        for (int i = 0; i < 8; i++) n1t += sh[i];
        const float L = __logf(se_t);
        const int lab = __ldg(labels + b);
        const float al = abl[lab];
        const float ace = -(0.9f * (al - bmax - L) +
                            1e-4f * (sa_t - (float)NC * (bmax + L)));
        float p1 = 0.f;
        if (n1t > 0.f) p1 = 1.f / (n1t + ((float)HW - n1t) * __expf(-10.f));
        g_ace[b] = ace;
        g_kld[b] = p1 * sk_t;
        __threadfence();
        const int done = atomicAdd(&g_done, 1);
        s_last = (done == NB - 1);
    }
    __syncthreads();

    // last block finishes: 64 -> 1 reduce, reset counter for next replay
    if (s_last && warp == 0) {
        __threadfence();   // acquire: see other blocks' g_ace/g_kld
        float a = g_ace[lane] + g_ace[lane + 32];
        float k = g_kld[lane] + g_kld[lane + 32];
        a = warpSum(a);
        k = warpSum(k);
        if (lane == 0) {
            out[0] = (a + 0.5f * k) * (1.0f / NB);
            g_done = 0;    // deterministic state for next graph replay
        }
    }
}

extern "C" void kernel_launch(void* const* d_in, const int* in_sizes, int n_in,
                              void* d_out, int out_size) {
    const float* cams  = (const float*)d_in[0];
    const int* y0      = (const int*)d_in[1];
    const int* labels  = (const int*)d_in[2];
    float* out = (float*)d_out;

    k1<<<dim3(NB, 25), 256>>>(cams, y0, labels);
    k2<<<NB, 256>>>(y0, labels, out);
}

// round 5
// speedup vs baseline: 1.1609x; 1.0096x over previous
#include <cuda_runtime.h>
#include <math_constants.h>

#define NB 64
#define NC 1000
#define HW 196
#define NF4 49
#define GY 25                             // blocks per batch
#define CPB (NC / GY)                     // 40 classes per block
#define C4L2E 5.770780163555852f          // 4 * log2(e)
#define LN2   0.6931471805599453f
#define L2E   1.4426950408889634f
#define CLIP2 (-19.931568569324174f)      // log2(1e-6)
#define DEADB (-12000.0f)                 // bias: 2^(u+DEADB) == 0

__device__ float g_abl[NB * NC];
__device__ float g_kp[NB * NC];
__device__ float g_ace[NB];
__device__ float g_kld[NB];
__device__ int   g_bcnt[NB];              // zero-initialized; reset by final block
__device__ int   g_done = 0;

__device__ __forceinline__ float ex2f(float x) {
    float r; asm("ex2.approx.f32 %0, %1;" : "=f"(r) : "f"(x)); return r;
}
__device__ __forceinline__ float warpSum(float v) {
#pragma unroll
    for (int o = 16; o; o >>= 1) v += __shfl_xor_sync(0xffffffffu, v, o);
    return v;
}
__device__ __forceinline__ float warpMax(float v) {
#pragma unroll
    for (int o = 16; o; o >>= 1) v = fmaxf(v, __shfl_xor_sync(0xffffffffu, v, o));
    return v;
}

// ---------------------------------------------------------------------------
// Single fused kernel. grid=(NB, GY), block=256 (8 warps, 5 rows/warp).
// Phase A: warp-per-row streaming pass (identical math to R4 k1).
// Phase B: the 25th block to finish a batch reduces that batch's 1000
//          ablation/kp values (L2-hot) to ace/kld.
// Phase C: the 64th batch-finisher reduces 64 partials to the scalar and
//          resets the counters for the next graph replay.
// All floating-point reduction orders are fixed -> deterministic.
// ---------------------------------------------------------------------------
__global__ __launch_bounds__(256, 6) void k1(const float* __restrict__ cams,
                                             const int* __restrict__ y0,
                                             const int* __restrict__ labels,
                                             float* __restrict__ out) {
    __shared__ float4 s_tn4[NF4];   // negated target row
    __shared__ float4 s_f4[NF4];    // fg mask as float
    __shared__ float sh[8];
    __shared__ float s_red;
    __shared__ int s_flag;

    const int b = blockIdx.x;
    const int tid = threadIdx.x;
    const int label = __ldg(labels + b);
    const float* base = cams + (size_t)b * NC * HW;

    if (tid < HW) {
        ((float*)s_tn4)[tid] = -__ldg(base + (size_t)label * HW + tid);
        ((float*)s_f4)[tid]  = (float)__ldg(y0 + b * HW + tid);
    }
    __syncthreads();

    const int warp = tid >> 5;
    const int lane = tid & 31;
    const bool live = lane < (NF4 - 32);
    const int idx2 = 32 + (live ? lane : 16);
    const float m1 = live ? 1.0f : 0.0f;
    const float bias1 = live ? 0.0f : DEADB;

    const float4 tn0 = s_tn4[lane];
    const float4 f0  = s_f4[lane];
    float4 tn1 = s_tn4[idx2];
    float4 f1  = s_f4[idx2];
    if (!live) { tn1 = make_float4(0.f,0.f,0.f,0.f); f1 = make_float4(0.f,0.f,0.f,0.f); }

    // row-invariant fg count
    float n1 = (f0.x + f0.y) + (f0.z + f0.w) + (f1.x + f1.y) + (f1.z + f1.w);
    n1 = warpSum(n1);

    const int c0 = blockIdx.y * CPB;
    const float4* row4 = (const float4*)(base + (size_t)(c0 + warp) * HW);
    const size_t rstep = (size_t)8 * NF4;

#pragma unroll 1
    for (int cl = warp; cl < CPB; cl += 8, row4 += rstep) {
        const float4 a0 = __ldg(row4 + lane);
        const float4 a1 = __ldg(row4 + idx2);

        float u[8];
        float den = 0.f, ap = 0.f, an = 0.f;

        {   // slot 0: always live
            float cv;
            cv = a0.x + tn0.x; u[0] = C4L2E * cv; den += ex2f(u[0]);
            ap += fabsf(cv); an = fmaf(f0.x, fabsf(cv) + cv, an);
            cv = a0.y + tn0.y; u[1] = C4L2E * cv; den += ex2f(u[1]);
            ap += fabsf(cv); an = fmaf(f0.y, fabsf(cv) + cv, an);
            cv = a0.z + tn0.z; u[2] = C4L2E * cv; den += ex2f(u[2]);
            ap += fabsf(cv); an = fmaf(f0.z, fabsf(cv) + cv, an);
            cv = a0.w + tn0.w; u[3] = C4L2E * cv; den += ex2f(u[3]);
            ap += fabsf(cv); an = fmaf(f0.w, fabsf(cv) + cv, an);
        }
        {   // slot 1: masked
            float cv;
            cv = a1.x + tn1.x; u[4] = fmaf(C4L2E, cv, bias1); den += ex2f(u[4]);
            ap = fmaf(m1, fabsf(cv), ap); an = fmaf(f1.x, fabsf(cv) + cv, an);
            cv = a1.y + tn1.y; u[5] = fmaf(C4L2E, cv, bias1); den += ex2f(u[5]);
            ap = fmaf(m1, fabsf(cv), ap); an = fmaf(f1.y, fabsf(cv) + cv, an);
            cv = a1.z + tn1.z; u[6] = fmaf(C4L2E, cv, bias1); den += ex2f(u[6]);
            ap = fmaf(m1, fabsf(cv), ap); an = fmaf(f1.z, fabsf(cv) + cv, an);
            cv = a1.w + tn1.w; u[7] = fmaf(C4L2E, cv, bias1); den += ex2f(u[7]);
            ap = fmaf(m1, fabsf(cv), ap); an = fmaf(f1.w, fabsf(cv) + cv, an);
        }

        den = warpSum(den);
        const float L2 = __log2f(den);
        const float Lc = L2 + CLIP2;

        float ka = 0.f;
        ka = fmaf(f0.x, fmaxf(u[0], Lc), ka);
        ka = fmaf(f0.y, fmaxf(u[1], Lc), ka);
        ka = fmaf(f0.z, fmaxf(u[2], Lc), ka);
        ka = fmaf(f0.w, fmaxf(u[3], Lc), ka);
        ka = fmaf(f1.x, fmaxf(u[4], Lc), ka);
        ka = fmaf(f1.y, fmaxf(u[5], Lc), ka);
        ka = fmaf(f1.z, fmaxf(u[6], Lc), ka);
        ka = fmaf(f1.w, fmaxf(u[7], Lc), ka);

        float abl = warpSum(ap - an);
        ka = warpSum(ka);

        if (lane == 0) {
            const int c = c0 + cl;
            g_abl[b * NC + c] = abl;
            g_kp[b * NC + c]  = -LN2 * (ka - n1 * L2);
        }
    }

    // ---------------- Phase B election: last block of this batch ------------
    __syncthreads();
    if (tid == 0) {
        __threadfence();                        // release our g_abl/g_kp stores
        s_flag = (atomicAdd(&g_bcnt[b], 1) == GY - 1);
    }
    __syncthreads();
    if (!s_flag) return;

    // ---------------- Phase B: per-batch reduction (L2-hot) -----------------
    __threadfence();                            // acquire peers' stores
    const float* abl = g_abl + b * NC;
    const float* kpp = g_kp + b * NC;

    float mx = -CUDART_INF_F;
    for (int c = tid; c < NC; c += 256) mx = fmaxf(mx, abl[c]);
    mx = warpMax(mx);
    if (lane == 0) sh[warp] = mx;
    __syncthreads();
    if (warp == 0) {
        float m2 = (lane < 8) ? sh[lane] : -CUDART_INF_F;
        m2 = warpMax(m2);
        if (lane == 0) s_red = m2;
    }
    __syncthreads();
    const float bmax = s_red;

    float se = 0.f, sa = 0.f, sk = 0.f;
    for (int c = tid; c < NC; c += 256) {
        const float a = abl[c];
        se += ex2f((a - bmax) * L2E);
        sa += a;
        sk += kpp[c];
    }
    se = warpSum(se); sa = warpSum(sa); sk = warpSum(sk);
    __syncthreads();
    if (lane == 0) { sh[warp] = se; }
    __syncthreads();
    if (tid == 0) { float t = 0.f; for (int i = 0; i < 8; i++) t += sh[i]; s_red = t; }
    __syncthreads();
    const float se_t = s_red;
    __syncthreads();
    if (lane == 0) { sh[warp] = sa; }
    __syncthreads();
    if (tid == 0) { float t = 0.f; for (int i = 0; i < 8; i++) t += sh[i]; s_red = t; }
    __syncthreads();
    const float sa_t = s_red;
    __syncthreads();
    if (lane == 0) { sh[warp] = sk; }
    __syncthreads();

    if (tid == 0) {
        float sk_t = 0.f;
        for (int i = 0; i < 8; i++) sk_t += sh[i];
        const float L = __logf(se_t);
        const float al = abl[label];
        const float ace = -(0.9f * (al - bmax - L) +
                            1e-4f * (sa_t - (float)NC * (bmax + L)));
        // n1 (warp 0's copy) equals the batch fg count
        float p1 = 0.f;
        if (n1 > 0.f) p1 = 1.f / (n1 + ((float)HW - n1) * __expf(-10.f));
        g_ace[b] = ace;
        g_kld[b] = p1 * sk_t;
        __threadfence();
        s_flag = (atomicAdd(&g_done, 1) == NB - 1);
    }
    __syncthreads();
    if (!s_flag) return;

    // ---------------- Phase C: final 64 -> 1 + counter reset ----------------
    if (warp == 0) {
        __threadfence();                        // acquire all g_ace/g_kld
        float a = g_ace[lane] + g_ace[lane + 32];
        float k = g_kld[lane] + g_kld[lane + 32];
        a = warpSum(a);
        k = warpSum(k);
        // reset counters for the next graph replay (all increments complete)
        g_bcnt[lane] = 0;
        g_bcnt[lane + 32] = 0;
        if (lane == 0) {
            out[0] = (a + 0.5f * k) * (1.0f / NB);
            g_done = 0;
        }
    }
}

extern "C" void kernel_launch(void* const* d_in, const int* in_sizes, int n_in,
                              void* d_out, int out_size) {
    const float* cams  = (const float*)d_in[0];
    const int* y0      = (const int*)d_in[1];
    const int* labels  = (const int*)d_in[2];
    float* out = (float*)d_out;

    k1<<<dim3(NB, GY), 256>>>(cams, y0, labels, out);
}

// round 7
// speedup vs baseline: 1.2575x; 1.0832x over previous
#include <cuda_runtime.h>
#include <math_constants.h>

#define NB 64
#define NC 1000
#define HW 196
#define NF4 49
#define GY 25                             // blocks per batch
#define CPB (NC / GY)                     // 40 classes per block
#define NKW (GY * 8)                      // kp partials per batch (200)
#define C4L2E 5.770780163555852f          // 4 * log2(e)
#define RC4L2E 0.17328679513998632f      // 1 / C4L2E
#define LN2   0.6931471805599453f
#define L2E   1.4426950408889634f
#define CLIP2 (-19.931568569324174f)      // log2(1e-6)
#define DEADB (-24000.0f)                 // u bias for dead lane-slots: 2^u == 0

__device__ float g_abl[NB * NC];
__device__ float g_kpw[NB * NKW];
__device__ float g_ace[NB];
__device__ float g_kld[NB];
__device__ int   g_bcnt[NB];              // zero-init; reset by final block
__device__ int   g_done = 0;

__device__ __forceinline__ float ex2f(float x) {
    float r; asm("ex2.approx.f32 %0, %1;" : "=f"(r) : "f"(x)); return r;
}
__device__ __forceinline__ float warpSum(float v) {
#pragma unroll
    for (int o = 16; o; o >>= 1) v += __shfl_xor_sync(0xffffffffu, v, o);
    return v;
}
__device__ __forceinline__ float warpMax(float v) {
#pragma unroll
    for (int o = 16; o; o >>= 1) v = fmaxf(v, __shfl_xor_sync(0xffffffffu, v, o));
    return v;
}

// ---------------------------------------------------------------------------
// Fused kernel. grid=(NB, GY), block=256 (8 warps, 5 rows/warp).
// Phase A (u-direct): u = C4L2E*a + tnu, tnu = C4L2E*(-target) (DEADB on dead
// lane-slots). Per row: den = sum 2^u -> L2; abl = (sum|u| - sum f2*max(u,0))
// / C4L2E. kp is summed over classes only, so per-lane kacc += f2*max(u,Lc)
// accumulates ACROSS rows; one butterfly at loop end gives a per-warp partial
//   kpw = -LN2*(0.5*kacc - n1*L2sum).
// Phase B: 25th block per batch reduces 1000 abl + 200 kpw partials.
// Phase C: 64th batch-finisher -> scalar; resets counters (replay-safe).
// All reduction orders fixed -> deterministic.
// ---------------------------------------------------------------------------
__global__ __launch_bounds__(256, 6) void k1(const float* __restrict__ cams,
                                             const int* __restrict__ y0,
                                             const int* __restrict__ labels,
                                             float* __restrict__ out) {
    __shared__ float4 s_tn4[NF4];   // tnu = -C4L2E * target row
    __shared__ float4 s_f4[NF4];    // f2 = 2 * fg mask
    __shared__ float sh_mx[8];
    __shared__ float sh_se[8];
    __shared__ float sh_sa[8];
    __shared__ float sh_sk[8];
    __shared__ float s_red;
    __shared__ int s_flag;

    const int b = blockIdx.x;
    const int tid = threadIdx.x;
    const int label = __ldg(labels + b);
    const float* base = cams + (size_t)b * NC * HW;

    if (tid < HW) {
        ((float*)s_tn4)[tid] = -C4L2E * __ldg(base + (size_t)label * HW + tid);
        ((float*)s_f4)[tid]  = 2.0f * (float)__ldg(y0 + b * HW + tid);
    }
    __syncthreads();

    const int warp = tid >> 5;
    const int lane = tid & 31;
    const bool live = lane < (NF4 - 32);
    const int idx2 = 32 + (live ? lane : 16);
    const float m1 = live ? 1.0f : 0.0f;

    const float4 tnu0 = s_tn4[lane];
    const float4 f0   = s_f4[lane];           // f2 values
    float4 tnu1, f1;
    if (live) { tnu1 = s_tn4[idx2]; f1 = s_f4[idx2]; }
    else {
        tnu1 = make_float4(DEADB, DEADB, DEADB, DEADB);
        f1   = make_float4(0.f, 0.f, 0.f, 0.f);
    }

    // row-invariant fg count: n1 = 0.5 * sum(f2)
    float n1 = 0.5f * ((f0.x + f0.y) + (f0.z + f0.w) +
                       (f1.x + f1.y) + (f1.z + f1.w));
    n1 = warpSum(n1);

    const int c0 = blockIdx.y * CPB;
    const float4* row4 = (const float4*)(base + (size_t)(c0 + warp) * HW);
    const size_t rstep = (size_t)8 * NF4;

    float kacc = 0.f;     // per-lane, across rows
    float L2sum = 0.f;    // per-row L2 accumulated (lane-uniform)

#pragma unroll 1
    for (int cl = warp; cl < CPB; cl += 8, row4 += rstep) {
        const float4 a0 = __ldg(row4 + lane);
        const float4 a1 = __ldg(row4 + idx2);

        float u[8];
        float den = 0.f, sabs = 0.f, sfp = 0.f;

        {   // slot 0: always live
            u[0] = fmaf(C4L2E, a0.x, tnu0.x); den += ex2f(u[0]);
            sabs += fabsf(u[0]); sfp = fmaf(f0.x, fmaxf(u[0], 0.f), sfp);
            u[1] = fmaf(C4L2E, a0.y, tnu0.y); den += ex2f(u[1]);
            sabs += fabsf(u[1]); sfp = fmaf(f0.y, fmaxf(u[1], 0.f), sfp);
            u[2] = fmaf(C4L2E, a0.z, tnu0.z); den += ex2f(u[2]);
            sabs += fabsf(u[2]); sfp = fmaf(f0.z, fmaxf(u[2], 0.f), sfp);
            u[3] = fmaf(C4L2E, a0.w, tnu0.w); den += ex2f(u[3]);
            sabs += fabsf(u[3]); sfp = fmaf(f0.w, fmaxf(u[3], 0.f), sfp);
        }
        {   // slot 1: |u| masked by m1; t/ka/den die arithmetically (DEADB,f=0)
            u[4] = fmaf(C4L2E, a1.x, tnu1.x); den += ex2f(u[4]);
            sabs = fmaf(m1, fabsf(u[4]), sabs); sfp = fmaf(f1.x, fmaxf(u[4], 0.f), sfp);
            u[5] = fmaf(C4L2E, a1.y, tnu1.y); den += ex2f(u[5]);
            sabs = fmaf(m1, fabsf(u[5]), sabs); sfp = fmaf(f1.y, fmaxf(u[5], 0.f), sfp);
            u[6] = fmaf(C4L2E, a1.z, tnu1.z); den += ex2f(u[6]);
            sabs = fmaf(m1, fabsf(u[6]), sabs); sfp = fmaf(f1.z, fmaxf(u[6], 0.f), sfp);
            u[7] = fmaf(C4L2E, a1.w, tnu1.w); den += ex2f(u[7]);
            sabs = fmaf(m1, fabsf(u[7]), sabs); sfp = fmaf(f1.w, fmaxf(u[7], 0.f), sfp);
        }

        den = warpSum(den);
        const float L2 = __log2f(den);
        const float Lc = L2 + CLIP2;
        L2sum += L2;

        kacc = fmaf(f0.x, fmaxf(u[0], Lc), kacc);
        kacc = fmaf(f0.y, fmaxf(u[1], Lc), kacc);
        kacc = fmaf(f0.z, fmaxf(u[2], Lc), kacc);
        kacc = fmaf(f0.w, fmaxf(u[3], Lc), kacc);
        kacc = fmaf(f1.x, fmaxf(u[4], Lc), kacc);
        kacc = fmaf(f1.y, fmaxf(u[5], Lc), kacc);
        kacc = fmaf(f1.z, fmaxf(u[6], Lc), kacc);
        kacc = fmaf(f1.w, fmaxf(u[7], Lc), kacc);

        const float s1 = warpSum(sabs - sfp);
        if (lane == 0) g_abl[b * NC + c0 + cl] = s1 * RC4L2E;
    }

    // one kp reduction per warp for its whole chunk
    kacc = warpSum(kacc);
    if (lane == 0)
        g_kpw[b * NKW + blockIdx.y * 8 + warp] =
            -LN2 * (0.5f * kacc - n1 * L2sum);

    // ---------------- Phase B election: last block of this batch ------------
    __syncthreads();
    if (tid == 0) {
        __threadfence();                        // release g_abl/g_kpw stores
        s_flag = (atomicAdd(&g_bcnt[b], 1) == GY - 1);
    }
    __syncthreads();
    if (!s_flag) return;

    // ---------------- Phase B: per-batch reduction (L2-hot) -----------------
    __threadfence();                            // acquire peers' stores
    const float* abl = g_abl + b * NC;
    const float* kwp = g_kpw + b * NKW;

    float mx = -CUDART_INF_F;
    for (int c = tid; c < NC; c += 256) mx = fmaxf(mx, abl[c]);
    mx = warpMax(mx);
    if (lane == 0) sh_mx[warp] = mx;
    __syncthreads();
    if (warp == 0) {
        float m2 = (lane < 8) ? sh_mx[lane] : -CUDART_INF_F;
        m2 = warpMax(m2);
        if (lane == 0) s_red = m2;
    }
    __syncthreads();
    const float bmax = s_red;

    float se = 0.f, sa = 0.f;
    for (int c = tid; c < NC; c += 256) {
        const float a = abl[c];
        se += ex2f((a - bmax) * L2E);
        sa += a;
    }
    float sk = (tid < NKW) ? kwp[tid] : 0.f;
    se = warpSum(se); sa = warpSum(sa); sk = warpSum(sk);
    if (lane == 0) { sh_se[warp] = se; sh_sa[warp] = sa; sh_sk[warp] = sk; }
    __syncthreads();

    if (tid == 0) {
        float se_t = 0.f, sa_t = 0.f, sk_t = 0.f;
        for (int i = 0; i < 8; i++) { se_t += sh_se[i]; sa_t += sh_sa[i]; sk_t += sh_sk[i]; }
        const float L = __logf(se_t);
        const float al = abl[label];
        const float ace = -(0.9f * (al - bmax - L) +
                            1e-4f * (sa_t - (float)NC * (bmax + L)));
        float p1 = 0.f;
        if (n1 > 0.f) p1 = 1.f / (n1 + ((float)HW - n1) * __expf(-10.f));
        g_ace[b] = ace;
        g_kld[b] = p1 * sk_t;
        __threadfence();
        s_flag = (atomicAdd(&g_done, 1) == NB - 1);
    }
    __syncthreads();
    if (!s_flag) return;

    // ---------------- Phase C: final 64 -> 1 + counter reset ----------------
    if (warp == 0) {
        __threadfence();                        // acquire all g_ace/g_kld
        float a = g_ace[lane] + g_ace[lane + 32];
        float k = g_kld[lane] + g_kld[lane + 32];
        a = warpSum(a);
        k = warpSum(k);
        g_bcnt[lane] = 0;
        g_bcnt[lane + 32] = 0;
        if (lane == 0) {
            out[0] = (a + 0.5f * k) * (1.0f / NB);
            g_done = 0;
        }
    }
}

extern "C" void kernel_launch(void* const* d_in, const int* in_sizes, int n_in,
                              void* d_out, int out_size) {
    const float* cams  = (const float*)d_in[0];
    const int* y0      = (const int*)d_in[1];
    const int* labels  = (const int*)d_in[2];
    float* out = (float*)d_out;

    k1<<<dim3(NB, GY), 256>>>(cams, y0, labels, out);
}